// round 14
// baseline (speedup 1.0000x reference)
#include <cuda_runtime.h>
#include <cuda_fp16.h>
#include <math.h>
#include <stdint.h>

// Fused flash-style self-attention via warp-level HMMA (mma.sync f16, sm_103-safe).
// R14 = R13 (key compaction, fp16 hi/lo, 3-term QK, 1-term PV, lazy-offset softmax)
//   + CROSS-TILE FUSION: PV(t) and QK(t+1) interleaved in one loop so each warp has
//   two independent MMA/LDSM streams (tensor and L1 pipes overlap instead of alternating).

namespace {

constexpr int B_ = 8;
constexpr int L_ = 2048;
constexpr int D_ = 256;
constexpr int BM = 128;          // queries per CTA
constexpr int BN = 64;           // keys per tile
constexpr int NT = 256;          // 8 warps
constexpr int NTILES = L_ / BN;  // 32 (max)
constexpr int TILE_BYTES = BN * 512;   // 32768

// smem byte offsets
constexpr int QHI   = 0;                    // 2 tile images (128 q-rows)
constexpr int QLO   = 65536;
constexpr int KBUF  = 131072;               // hi buffers 0/1 at +0, +32768
constexpr int KLOB  = 196608;               // lo buffer (single)
constexpr int GIDX  = 229376;               // 2 x 128B gidx ring
constexpr int SMEM_TOTAL = 229632;

constexpr float L2E = 1.4426950408889634f;

// pre-split, pre-swizzled x (original order): [b][tile][32768]
__device__ unsigned char g_xhi[B_ * NTILES * TILE_BYTES];
__device__ unsigned char g_xlo[B_ * NTILES * TILE_BYTES];
// compacted key images: [b][tile][32768]
__device__ unsigned char g_khi[B_ * NTILES * TILE_BYTES];
__device__ unsigned char g_klo[B_ * NTILES * TILE_BYTES];
// compacted slot -> original key index (-1 = padding): [b][2048]
__device__ __align__(16) short g_kidx[B_ * L_];
__device__ int g_ntiles[B_];

// ---------------- helpers ----------------

__device__ __forceinline__ uint32_t smem_u32(const void* p) {
  uint32_t a;
  asm("{ .reg .u64 t; cvta.to.shared.u64 t, %1; cvt.u32.u64 %0, t; }" : "=r"(a) : "l"(p));
  return a;
}

// swizzled byte offset for (row, d) with row<64, d multiple of 8 (fp16 elems)
__device__ __forceinline__ uint32_t swoff8(int row, int d) {
  return (uint32_t)(row * 512) + ((((uint32_t)(d >> 3) ^ (uint32_t)(row & 7)) << 4));
}

__device__ __forceinline__ void ldsm4(uint32_t (&r)[4], uint32_t addr) {
  asm volatile("ldmatrix.sync.aligned.m8n8.x4.shared.b16 {%0,%1,%2,%3}, [%4];"
               : "=r"(r[0]), "=r"(r[1]), "=r"(r[2]), "=r"(r[3]) : "r"(addr));
}
__device__ __forceinline__ void ldsm4t(uint32_t (&r)[4], uint32_t addr) {
  asm volatile("ldmatrix.sync.aligned.m8n8.x4.trans.shared.b16 {%0,%1,%2,%3}, [%4];"
               : "=r"(r[0]), "=r"(r[1]), "=r"(r[2]), "=r"(r[3]) : "r"(addr));
}

__device__ __forceinline__ void mma16816(float (&d)[4], const uint32_t (&a)[4],
                                         uint32_t b0, uint32_t b1) {
  asm volatile(
    "mma.sync.aligned.m16n8k16.row.col.f32.f16.f16.f32 "
    "{%0,%1,%2,%3}, {%4,%5,%6,%7}, {%8,%9}, {%0,%1,%2,%3};"
    : "+f"(d[0]), "+f"(d[1]), "+f"(d[2]), "+f"(d[3])
    : "r"(a[0]), "r"(a[1]), "r"(a[2]), "r"(a[3]), "r"(b0), "r"(b1));
}

__device__ __forceinline__ void split2h(float a, float b, uint32_t& hi, uint32_t& lo) {
  __half ah = __float2half_rn(a);
  __half bh = __float2half_rn(b);
  float ar = a - __half2float(ah);
  float br = b - __half2float(bh);
  __half2 h; h.x = ah; h.y = bh;
  __half2 l; l.x = __float2half_rn(ar); l.y = __float2half_rn(br);
  hi = *reinterpret_cast<uint32_t*>(&h);
  lo = *reinterpret_cast<uint32_t*>(&l);
}

__device__ __forceinline__ uint32_t packh2(float a, float b) {
  __half2 h = __floats2half2_rn(a, b);
  return *reinterpret_cast<uint32_t*>(&h);
}

// exp(s - off) via exp2 polynomial; c = off * log2(e). s = -inf -> ~0.
__device__ __forceinline__ float exp_off(float s, float c) {
  float t = fmaf(s, L2E, -c);
  t = fmaxf(t, -120.f);
  int e = __float2int_rn(t);
  float f = t - (float)e;
  float r = 1.535336188319500e-4f;
  r = fmaf(r, f, 1.339887440266574e-3f);
  r = fmaf(r, f, 9.618437357674640e-3f);
  r = fmaf(r, f, 5.550332471162809e-2f);
  r = fmaf(r, f, 2.402264791363012e-1f);
  r = fmaf(r, f, 6.931472028550421e-1f);
  r = fmaf(r, f, 1.0f);
  return r * __int_as_float((e + 127) << 23);
}

__device__ __forceinline__ void cpa16(uint32_t dst, const void* src) {
  asm volatile("cp.async.cg.shared.global [%0], [%1], 16;" :: "r"(dst), "l"(src));
}
#define CP_COMMIT() asm volatile("cp.async.commit_group;" ::: "memory")
#define CP_WAIT0()  asm volatile("cp.async.wait_group 0;" ::: "memory")

__device__ __forceinline__ void issue_tile(uint32_t smem_dst, const unsigned char* gsrc, int tid) {
  const unsigned char* src = gsrc + tid * 128;
  uint32_t dst = smem_dst + tid * 128;
  #pragma unroll
  for (int j = 0; j < 8; j++) cpa16(dst + j * 16, src + j * 16);
}

// ---- scan: detect mask dtype + compact unmasked key indices ----
__global__ void scan_mask_kernel(const void* __restrict__ xmask)
{
  const int b   = blockIdx.x;
  const int tid = threadIdx.x;

  const unsigned int* mw = (const unsigned int*)xmask;
  int not32 = 0, notbyte = 0;
  for (int i = tid; i < 2048; i += 256) {
    unsigned int w = mw[i];
    if (w > 1u) not32 = 1;
    #pragma unroll
    for (int k = 0; k < 4; k++)
      if (((w >> (8 * k)) & 0xFFu) > 1u) notbyte = 1;
  }
  __shared__ int s32, sbyte;
  if (tid == 0) { s32 = 0; sbyte = 0; }
  __syncthreads();
  if (not32)   atomicOr(&s32, 1);
  if (notbyte) atomicOr(&sbyte, 1);
  __syncthreads();
  const int mtype = (!s32) ? 0 : (!sbyte ? 1 : 2);

  int flags[8], cnt = 0;
  #pragma unroll
  for (int k = 0; k < 8; k++) {
    const int i = tid * 8 + k;
    const size_t gi = (size_t)b * L_ + i;
    int masked;
    if (mtype == 0)      masked = ((const int*)xmask)[gi] != 0;
    else if (mtype == 1) masked = ((const unsigned char*)xmask)[gi] != 0;
    else                 masked = ((const float*)xmask)[gi] != 0.f;
    flags[k] = !masked;
    cnt += flags[k];
  }

  const int lane = tid & 31, wid = tid >> 5;
  int pre = cnt;
  #pragma unroll
  for (int o = 1; o < 32; o <<= 1) {
    int v = __shfl_up_sync(0xffffffffu, pre, o);
    if (lane >= o) pre += v;
  }
  const int excl = pre - cnt;
  __shared__ int wsum[8];
  if (lane == 31) wsum[wid] = pre;
  __syncthreads();
  int wbase = 0;
  for (int k = 0; k < wid; k++) wbase += wsum[k];

  int r = wbase + excl;
  #pragma unroll
  for (int k = 0; k < 8; k++) {
    if (flags[k]) { g_kidx[b * L_ + r] = (short)(tid * 8 + k); r++; }
  }

  __shared__ int total_s;
  if (tid == 255) total_s = wbase + pre;
  __syncthreads();
  const int n = total_s;
  const int npad = (n + 63) & ~63;
  for (int s = n + tid; s < npad; s += 256) g_kidx[b * L_ + s] = -1;
  if (tid == 0) g_ntiles[b] = npad >> 6;
}

// ---- pre-pass: split x into fp16 hi/lo swizzled tile images ----
__global__ void split_x_kernel(const float* __restrict__ x)
{
  const int idx = blockIdx.x * blockDim.x + threadIdx.x;
  const int d8 = idx & 31;
  const int r  = (idx >> 5) & (L_ - 1);
  const int b  = idx >> 16;
  const float* src = x + ((size_t)(b * L_ + r)) * D_ + d8 * 8;
  float4 v0 = *reinterpret_cast<const float4*>(src);
  float4 v1 = *reinterpret_cast<const float4*>(src + 4);
  uint32_t h[4], l[4];
  split2h(v0.x, v0.y, h[0], l[0]);
  split2h(v0.z, v0.w, h[1], l[1]);
  split2h(v1.x, v1.y, h[2], l[2]);
  split2h(v1.z, v1.w, h[3], l[3]);
  const int tile = r >> 6;
  const uint32_t off = ((uint32_t)(b * NTILES + tile) << 15) + swoff8(r & 63, d8 * 8);
  *reinterpret_cast<uint4*>(g_xhi + off) = make_uint4(h[0], h[1], h[2], h[3]);
  *reinterpret_cast<uint4*>(g_xlo + off) = make_uint4(l[0], l[1], l[2], l[3]);
}

// ---- gather compacted key rows (pure copy from the already-split images) ----
__global__ void gather_k_kernel()
{
  const int idx  = blockIdx.x * blockDim.x + threadIdx.x;
  const int d8   = idx & 31;
  const int slot = (idx >> 5) & (L_ - 1);
  const int b    = idx >> 16;
  if (slot >= g_ntiles[b] * BN) return;
  const int src = g_kidx[b * L_ + slot];
  const uint32_t doff = ((uint32_t)(b * NTILES + (slot >> 6)) << 15) + swoff8(slot & 63, d8 * 8);
  if (src < 0) {
    *reinterpret_cast<uint4*>(g_khi + doff) = make_uint4(0, 0, 0, 0);
    *reinterpret_cast<uint4*>(g_klo + doff) = make_uint4(0, 0, 0, 0);
    return;
  }
  const uint32_t soff = ((uint32_t)(b * NTILES + (src >> 6)) << 15) + swoff8(src & 63, d8 * 8);
  *reinterpret_cast<uint4*>(g_khi + doff) = *reinterpret_cast<const uint4*>(g_xhi + soff);
  *reinterpret_cast<uint4*>(g_klo + doff) = *reinterpret_cast<const uint4*>(g_xlo + soff);
}

// ---------------- main kernel ----------------

__global__ void __launch_bounds__(NT, 1)
attn_hmma_kernel(float* __restrict__ out)
{
  extern __shared__ char sm[];
  const uint32_t smb = smem_u32(sm);

  const int b    = blockIdx.y;
  const int q0   = blockIdx.x * BM;
  const int tid  = threadIdx.x;
  const int w    = tid >> 5;
  const int lane = tid & 31;
  const int ntiles = g_ntiles[b];

  // ---- prologue: Q (2 tiles hi+lo), K tile 0 hi+lo, gidx tile 0 ----
  {
    const int qt = (b * NTILES) + (q0 >> 6);
    issue_tile(smb + QHI,         g_xhi + ((size_t)qt << 15), tid);
    issue_tile(smb + QHI + 32768, g_xhi + ((size_t)(qt + 1) << 15), tid);
    issue_tile(smb + QLO,         g_xlo + ((size_t)qt << 15), tid);
    issue_tile(smb + QLO + 32768, g_xlo + ((size_t)(qt + 1) << 15), tid);
    issue_tile(smb + KBUF, g_khi + ((size_t)(b * NTILES) << 15), tid);
    issue_tile(smb + KLOB, g_klo + ((size_t)(b * NTILES) << 15), tid);
    if (tid < 8)
      cpa16(smb + GIDX + tid * 16,
            (const unsigned char*)g_kidx + (size_t)b * L_ * 2 + tid * 16);
    CP_COMMIT();
    CP_WAIT0();
  }
  __syncthreads();

  // lane decomposition
  const int g  = lane >> 2;
  const int t4 = lane & 3;
  const int m  = lane >> 3;
  const int i8 = lane & 7;

  const int rowA  = 16 * w + (m & 1) * 8 + i8;
  const int dAoff = (m >> 1) * 8;
  const int keyB  = (m >> 1) * 8 + i8;
  const int dBoff = (m & 1) * 8;
  const int keyV  = (m & 1) * 8 + i8;
  const int dVoff = (m >> 1) * 8;

  const uint32_t qimg = (uint32_t)((rowA >> 6) << 15);
  const int rA = rowA & 63;

  const int qa = q0 + 16 * w + g;
  const int qb = qa + 8;

  float o[32][4];
  #pragma unroll
  for (int n = 0; n < 32; n++)
    #pragma unroll
    for (int c = 0; c < 4; c++) o[n][c] = 0.f;
  float rs0 = 0.f, rs1 = 0.f;
  float off0 = 0.f, off1 = 0.f;
  float c0 = 0.f, c1 = 0.f;

  float s[8][4];
  #pragma unroll
  for (int n = 0; n < 8; n++)
    #pragma unroll
    for (int c = 0; c < 4; c++) s[n][c] = 0.f;

  // ---- QK(0) standalone ----
  if (ntiles > 0) {
    #pragma unroll
    for (int kc = 0; kc < 16; kc++) {
      uint32_t ahi[4], alo[4];
      uint32_t aoff = qimg + swoff8(rA, kc * 16 + dAoff);
      ldsm4(ahi, smb + QHI + aoff);
      ldsm4(alo, smb + QLO + aoff);
      #pragma unroll
      for (int np = 0; np < 2; np++) {
        uint32_t bhi0[4], blo0[4], bhi1[4], blo1[4];
        uint32_t boff0 = swoff8(keyB + 32 * np,      kc * 16 + dBoff);
        uint32_t boff1 = swoff8(keyB + 32 * np + 16, kc * 16 + dBoff);
        ldsm4(bhi0, smb + KBUF + boff0);
        ldsm4(blo0, smb + KLOB + boff0);
        ldsm4(bhi1, smb + KBUF + boff1);
        ldsm4(blo1, smb + KLOB + boff1);
        mma16816(s[4*np+0], ahi, bhi0[0], bhi0[1]);
        mma16816(s[4*np+1], ahi, bhi0[2], bhi0[3]);
        mma16816(s[4*np+2], ahi, bhi1[0], bhi1[1]);
        mma16816(s[4*np+3], ahi, bhi1[2], bhi1[3]);
        mma16816(s[4*np+0], ahi, blo0[0], blo0[1]);
        mma16816(s[4*np+1], ahi, blo0[2], blo0[3]);
        mma16816(s[4*np+2], ahi, blo1[0], blo1[1]);
        mma16816(s[4*np+3], ahi, blo1[2], blo1[3]);
        mma16816(s[4*np+0], alo, bhi0[0], bhi0[1]);
        mma16816(s[4*np+1], alo, bhi0[2], bhi0[3]);
        mma16816(s[4*np+2], alo, bhi1[0], bhi1[1]);
        mma16816(s[4*np+3], alo, bhi1[2], bhi1[3]);
      }
    }
  }
  __syncthreads();   // lo(0) consumed by all warps

  if (ntiles > 1) {
    issue_tile(smb + KBUF + 32768, g_khi + ((size_t)(b * NTILES + 1) << 15), tid);
    issue_tile(smb + KLOB,         g_klo + ((size_t)(b * NTILES + 1) << 15), tid);
    if (tid < 8)
      cpa16(smb + GIDX + 128 + tid * 16,
            (const unsigned char*)g_kidx + (size_t)b * L_ * 2 + 128 + tid * 16);
    CP_COMMIT();
  }

  for (int t = 0; t < ntiles; ++t) {
    const uint32_t kHiCur = smb + KBUF + (uint32_t)((t & 1) << 15);
    const uint32_t gOff = (uint32_t)(GIDX + ((t & 1) << 7));

    // ---- softmax(t): pass 1 (diag/mask/max) ----
    float lm0 = -INFINITY, lm1 = -INFINITY;
    #pragma unroll
    for (int nt = 0; nt < 8; nt++) {
      const int col0 = 8 * nt + 2 * t4;
      const uint32_t gw = *reinterpret_cast<const uint32_t*>(sm + gOff + col0 * 2);
      const int gi0 = (int)(short)(gw & 0xFFFFu);
      const int gi1 = (int)(short)(gw >> 16);

      float v0 = (gi0 == qa) ? 0.f : s[nt][0];
      float v1 = (gi1 == qa) ? 0.f : s[nt][1];
      float v2 = (gi0 == qb) ? 0.f : s[nt][2];
      float v3 = (gi1 == qb) ? 0.f : s[nt][3];
      if (gi0 < 0) { v0 = -INFINITY; v2 = -INFINITY; }
      if (gi1 < 0) { v1 = -INFINITY; v3 = -INFINITY; }
      s[nt][0] = v0; s[nt][1] = v1; s[nt][2] = v2; s[nt][3] = v3;
      lm0 = fmaxf(lm0, fmaxf(v0, v1));
      lm1 = fmaxf(lm1, fmaxf(v2, v3));
    }
    lm0 = fmaxf(lm0, __shfl_xor_sync(0xffffffffu, lm0, 1));
    lm0 = fmaxf(lm0, __shfl_xor_sync(0xffffffffu, lm0, 2));
    lm1 = fmaxf(lm1, __shfl_xor_sync(0xffffffffu, lm1, 1));
    lm1 = fmaxf(lm1, __shfl_xor_sync(0xffffffffu, lm1, 2));

    // ---- lazy offset raise ----
    const bool r0 = lm0 > off0 + 10.f;
    const bool r1 = lm1 > off1 + 10.f;
    if (r0 || r1) {
      const float no0 = r0 ? (lm0 - 6.f) : off0;
      const float no1 = r1 ? (lm1 - 6.f) : off1;
      const float a0 = __expf(off0 - no0);
      const float a1 = __expf(off1 - no1);
      off0 = no0; off1 = no1;
      c0 = off0 * L2E; c1 = off1 * L2E;
      rs0 *= a0; rs1 *= a1;
      #pragma unroll
      for (int n = 0; n < 32; n++) {
        o[n][0] *= a0; o[n][1] *= a0;
        o[n][2] *= a1; o[n][3] *= a1;
      }
    }

    // ---- pass 2: exp, row sums, pack P ----
    uint32_t phi[4][4];
    #pragma unroll
    for (int nt = 0; nt < 8; nt++) {
      float p0 = exp_off(s[nt][0], c0);
      float p1 = exp_off(s[nt][1], c0);
      float p2 = exp_off(s[nt][2], c1);
      float p3 = exp_off(s[nt][3], c1);
      rs0 += p0 + p1;
      rs1 += p2 + p3;
      const int kc = nt >> 1;
      if ((nt & 1) == 0) {
        phi[kc][0] = packh2(p0, p1);
        phi[kc][1] = packh2(p2, p3);
      } else {
        phi[kc][2] = packh2(p0, p1);
        phi[kc][3] = packh2(p2, p3);
      }
    }

    if (t + 1 < ntiles) {
      CP_WAIT0();
      __syncthreads();   // hi(t+1), lo(t+1), gidx(t+1) landed
      const uint32_t kHiNext = smb + KBUF + (uint32_t)(((t + 1) & 1) << 15);

      // ---- FUSED: QK(t+1) + PV(t), interleaved dual streams ----
      #pragma unroll
      for (int n = 0; n < 8; n++)
        #pragma unroll
        for (int c = 0; c < 4; c++) s[n][c] = 0.f;

      uint32_t ahi[4], alo[4];
      #pragma unroll
      for (int fi = 0; fi < 32; ++fi) {
        const int kc  = fi >> 1, np  = fi & 1;   // QK indices
        const int kcp = fi >> 3, npp = fi & 7;   // PV indices

        if (np == 0) {
          uint32_t aoff = qimg + swoff8(rA, kc * 16 + dAoff);
          ldsm4(ahi, smb + QHI + aoff);
          ldsm4(alo, smb + QLO + aoff);
        }
        uint32_t bhi0[4], blo0[4], bhi1[4], blo1[4];
        uint32_t boff0 = swoff8(keyB + 32 * np,      kc * 16 + dBoff);
        uint32_t boff1 = swoff8(keyB + 32 * np + 16, kc * 16 + dBoff);
        ldsm4(bhi0, kHiNext + boff0);
        ldsm4(blo0, smb + KLOB + boff0);
        ldsm4(bhi1, kHiNext + boff1);
        ldsm4(blo1, smb + KLOB + boff1);

        uint32_t vh0[4], vh1[4];
        const int dcol = 32 * npp + dVoff;
        ldsm4t(vh0, kHiCur + swoff8(16 * kcp + keyV, dcol));
        ldsm4t(vh1, kHiCur + swoff8(16 * kcp + keyV, dcol + 16));

        float (*sp)[4] = &s[4 * np];
        float (*op)[4] = &o[4 * npp];
        // interleave the two independent MMA streams
        mma16816(sp[0], ahi, bhi0[0], bhi0[1]);
        mma16816(sp[1], ahi, bhi0[2], bhi0[3]);
        mma16816(op[0], phi[kcp], vh0[0], vh0[1]);
        mma16816(sp[2], ahi, bhi1[0], bhi1[1]);
        mma16816(sp[3], ahi, bhi1[2], bhi1[3]);
        mma16816(op[1], phi[kcp], vh0[2], vh0[3]);
        mma16816(sp[0], ahi, blo0[0], blo0[1]);
        mma16816(sp[1], ahi, blo0[2], blo0[3]);
        mma16816(op[2], phi[kcp], vh1[0], vh1[1]);
        mma16816(sp[2], ahi, blo1[0], blo1[1]);
        mma16816(sp[3], ahi, blo1[2], blo1[3]);
        mma16816(op[3], phi[kcp], vh1[2], vh1[3]);
        mma16816(sp[0], alo, bhi0[0], bhi0[1]);
        mma16816(sp[1], alo, bhi0[2], bhi0[3]);
        mma16816(sp[2], alo, bhi1[0], bhi1[1]);
        mma16816(sp[3], alo, bhi1[2], bhi1[3]);
      }

      __syncthreads();   // hi(t) dead, lo(t+1) consumed

      // prefetch t+2 (hi into buffer t&1, lo into single buffer, gidx into ring t&1)
      if (t + 2 < ntiles) {
        issue_tile(smb + KBUF + (uint32_t)((t & 1) << 15),
                   g_khi + ((size_t)(b * NTILES + t + 2) << 15), tid);
        issue_tile(smb + KLOB,
                   g_klo + ((size_t)(b * NTILES + t + 2) << 15), tid);
        if (tid < 8)
          cpa16(smb + GIDX + (uint32_t)((t & 1) << 7) + tid * 16,
                (const unsigned char*)g_kidx + (size_t)b * L_ * 2 + (size_t)(t + 2) * 128 + tid * 16);
        CP_COMMIT();
      }
    } else {
      // ---- last tile: PV only ----
      #pragma unroll
      for (int kc = 0; kc < 4; kc++) {
        #pragma unroll
        for (int np = 0; np < 8; np++) {
          uint32_t vh0[4], vh1[4];
          const int dcol = 32 * np + dVoff;
          ldsm4t(vh0, kHiCur + swoff8(16 * kc + keyV, dcol));
          ldsm4t(vh1, kHiCur + swoff8(16 * kc + keyV, dcol + 16));
          mma16816(o[4*np+0], phi[kc], vh0[0], vh0[1]);
          mma16816(o[4*np+1], phi[kc], vh0[2], vh0[3]);
          mma16816(o[4*np+2], phi[kc], vh1[0], vh1[1]);
          mma16816(o[4*np+3], phi[kc], vh1[2], vh1[3]);
        }
      }
    }
  }

  // ---- epilogue: reduce row sums over the quad, normalize, store ----
  rs0 += __shfl_xor_sync(0xffffffffu, rs0, 1);
  rs0 += __shfl_xor_sync(0xffffffffu, rs0, 2);
  rs1 += __shfl_xor_sync(0xffffffffu, rs1, 1);
  rs1 += __shfl_xor_sync(0xffffffffu, rs1, 2);
  const float inv0 = (rs0 > 0.f) ? (1.f / rs0) : 0.f;
  const float inv1 = (rs1 > 0.f) ? (1.f / rs1) : 0.f;

  float* outa = out + ((size_t)b * L_ + qa) * D_;
  float* outb = out + ((size_t)b * L_ + qb) * D_;
  #pragma unroll
  for (int nt = 0; nt < 32; nt++) {
    const int dcol = 8 * nt + 2 * t4;
    float2 va; va.x = o[nt][0] * inv0; va.y = o[nt][1] * inv0;
    float2 vb; vb.x = o[nt][2] * inv1; vb.y = o[nt][3] * inv1;
    *reinterpret_cast<float2*>(outa + dcol) = va;
    *reinterpret_cast<float2*>(outb + dcol) = vb;
  }
}

} // namespace

extern "C" void kernel_launch(void* const* d_in, const int* in_sizes, int n_in,
                              void* d_out, int out_size)
{
  const float* x     = (const float*)d_in[0];
  const void*  xmask = d_in[1];
  float*       out   = (float*)d_out;

  scan_mask_kernel<<<B_, 256>>>(xmask);
  split_x_kernel<<<(B_ * L_ * D_ / 8) / 256, 256>>>(x);
  gather_k_kernel<<<(B_ * L_ * D_ / 8) / 256, 256>>>();

  cudaFuncSetAttribute(attn_hmma_kernel, cudaFuncAttributeMaxDynamicSharedMemorySize, SMEM_TOTAL);
  dim3 grid(L_ / BM, B_);
  attn_hmma_kernel<<<grid, NT, SMEM_TOTAL>>>(out);
}